// round 8
// baseline (speedup 1.0000x reference)
#include <cuda_runtime.h>
#include <math.h>

// Problem constants (fixed by the reference)
#define Bn    8
#define Tn    128
#define Un    64
#define U1    65
#define Vn    1024
#define BLANKC 1023
#define NEGF  (-1e30f)
#define LOG2E 1.44269504088896340736f
#define LN2F  0.69314718055994530942f
#define RING  88     // shared ring slots (>= 66-row live window + 22 slack)
#define RW    132    // floats per ring row: lpb[0..64] | pad | lpe at 66..130 | pad

// Scratch (BSS zero-init; dead rows stay 0 forever -> deterministic).
__device__ float g_lpb[Bn * Tn * U1];   // log2-domain blank log-probs
__device__ float g_lpe[Bn * Tn * Un];   // log2-domain emit  log-probs
__device__ int   g_cnt[Bn * Tn];        // per-(b,t) completion counters

__device__ __forceinline__ int ld_acq_gpu(const int* p) {
    int v; asm volatile("ld.acquire.gpu.u32 %0, [%1];" : "=r"(v) : "l"(p) : "memory");
    return v;
}
__device__ __forceinline__ int ld_acq_cta_sh(unsigned a) {
    int v; asm volatile("ld.acquire.cta.shared.u32 %0, [%1];" : "=r"(v) : "r"(a) : "memory");
    return v;
}
// log2-domain logaddexp. Args finite (NEGF sentinel), mn-mx <= 0.
__device__ __forceinline__ float laexp2(float x, float y) {
    const float mx = fmaxf(x, y);          // NaN-safe: fmaxf/fminf drop NaN
    const float mn = fminf(x, y);
    return mx + __log2f(1.0f + exp2f(mn - mx));
}
__device__ __forceinline__ int clampt(int t) { return min(max(t, 0), Tn - 1); }
__device__ __forceinline__ int ringslot(int x) { return (x >= RING) ? x - RING : x; }

// ---------------------------------------------------------------------------
// Fused kernel.
//  blockIdx < 8  : DP role (warp0 = wavefront, warps 1-2 = row stagers)
//  blockIdx >= 8 : A role (one warp per LIVE (b,t,u) row, t-major order)
// ---------------------------------------------------------------------------
__global__ void __launch_bounds__(256)
fused_kernel(const float* __restrict__ logits,
             const int* __restrict__ targets,
             const int* __restrict__ logit_lengths,
             const int* __restrict__ target_lengths,
             float* __restrict__ out)
{
    __shared__ float s_lp[RING * RW];
    __shared__ int   s_prog[2];

    if (blockIdx.x >= Bn) {
        // =================== A role: logsumexp + gather ===================
        const int w    = (blockIdx.x - Bn) * 8 + (threadIdx.x >> 5);
        const int lane = threadIdx.x & 31;
        const int t    = w / (Bn * U1);          // t-major sweep
        const int rem  = w - t * (Bn * U1);
        const int b    = rem / U1;
        const int u    = rem - b * U1;

        // Skip rows the DP never consumes (warp-uniform predicate).
        if (t >= logit_lengths[b] || u > target_lengths[b]) return;

        const size_t row = ((size_t)(b * Tn + t) * U1 + u);
        const float4* row4 = reinterpret_cast<const float4*>(logits + row * Vn);

        float4 v[8];
#pragma unroll
        for (int i = 0; i < 8; i++) v[i] = row4[lane + 32 * i];

        float m = -INFINITY;
#pragma unroll
        for (int i = 0; i < 8; i++)
            m = fmaxf(m, fmaxf(fmaxf(v[i].x, v[i].y), fmaxf(v[i].z, v[i].w)));
#pragma unroll
        for (int o = 16; o > 0; o >>= 1)
            m = fmaxf(m, __shfl_xor_sync(0xffffffffu, m, o));

        float s = 0.f;
#pragma unroll
        for (int i = 0; i < 8; i++)
            s += __expf(v[i].x - m) + __expf(v[i].y - m)
               + __expf(v[i].z - m) + __expf(v[i].w - m);
#pragma unroll
        for (int o = 16; o > 0; o >>= 1)
            s += __shfl_xor_sync(0xffffffffu, s, o);

        if (lane == 0) {
            const float lse  = m + logf(s);
            const float* rowf = logits + row * Vn;
            g_lpb[row] = (rowf[BLANKC] - lse) * LOG2E;
            if (u < Un) {
                const int tgt = targets[b * Un + u];
                g_lpe[(b * Tn + t) * Un + u] = (rowf[tgt] - lse) * LOG2E;
            }
            __threadfence();                       // release
            atomicAdd(&g_cnt[b * Tn + t], 1);
        }
        return;
    }

    // ====================== DP role (one block per batch) ======================
    const int b    = blockIdx.x;
    const int wid  = threadIdx.x >> 5;
    const int lane = threadIdx.x & 31;
    if (wid > 2) return;

    const int tl = logit_lengths[b];       // in [64,128]
    const int ul = target_lengths[b];      // in [32,64]

    if (wid >= 1) {
        // ---------------- stagers: warps 1,2 handle rows r = wid-1 (mod 2) ----
        const int ws = wid - 1;
        const float* lpb_g = g_lpb + b * Tn * U1;
        const float* lpe_g = g_lpe + b * Tn * Un;
        int prog = 0;
        for (int r = ws; r < Tn; r += 2) {
            if (r < tl) {
                const int* cp = &g_cnt[b * Tn + r];
                const int expected = ul + 1;
                if (lane == 0) {
                    while (ld_acq_gpu(cp) < expected) { }
                    *(volatile int*)cp = 0;        // reset for next replay
                }
                __syncwarp();                      // broadcast acquire to warp
                float* dst = s_lp + ringslot(r) * RW;
                dst[lane]        = lpb_g[r * U1 + lane];
                dst[lane + 32]   = lpb_g[r * U1 + lane + 32];
                if (lane == 0) dst[64] = lpb_g[r * U1 + 64];
                dst[66 + lane]       = lpe_g[r * Un + lane];
                dst[66 + lane + 32]  = lpe_g[r * Un + lane + 32];
            }
            __syncwarp();
            __threadfence_block();                 // order STS before prog
            prog++;
            if (lane == 0) s_prog[ws] = prog;
        }
        return;
    }

    // ---------------- warp 0: branchless wavefront (log2 domain) ----------
    if (lane == 0) { s_prog[0] = 0; s_prog[1] = 0; }
    __syncwarp();
    const unsigned prog_addr =
        (unsigned)__cvta_generic_to_shared(&s_prog[0]);

    const int t_last = tl - 1;
    const int u_last = ul;
    const int d_star = t_last + u_last;            // in [95, 191]
    const unsigned FULL = 0xffffffffu;
    const int um1_0 = max(lane - 1, 0);

    float a0 = (lane == 0) ? 0.f : NEGF;           // u = lane
    float a1 = NEGF;                               // u = lane + 32
    float a2 = NEGF;                               // u = 64 (replicated)
    int r_ok = 0;

    for (int d = 1; d <= d_star; d++) {
        // gate: rows 0..min(d,127) must be staged
        const int need = min(d, Tn - 1) + 1;
        while (r_ok < need) {
            const int k0 = ld_acq_cta_sh(prog_addr);
            const int k1 = ld_acq_cta_sh(prog_addr + 4);
            r_ok = min(2 * k0, 2 * k1 + 1);
        }

        float p0        = __shfl_up_sync(FULL, a0, 1);
        const float b31 = __shfl_sync(FULL, a0, 31);
        float p1        = __shfl_up_sync(FULL, a1, 1);
        const float p2  = __shfl_sync(FULL, a1, 31);
        if (lane == 0) { p0 = NEGF; p1 = b31; }

        {   // segment 0: u = lane
            const int t  = d - lane;
            const int rb = ringslot(clampt(t - 1));
            const int re = ringslot(clampt(t));
            const float up = a0 + s_lp[rb * RW + lane];
            const float lf = p0 + s_lp[re * RW + 66 + um1_0];
            a0 = laexp2(up, lf);
        }
        {   // segment 1: u = lane + 32
            const int t  = d - lane - 32;
            const int rb = ringslot(clampt(t - 1));
            const int re = ringslot(clampt(t));
            const float up = a1 + s_lp[rb * RW + lane + 32];
            const float lf = p1 + s_lp[re * RW + 66 + lane + 31];
            a1 = laexp2(up, lf);
        }
        {   // segment 2: u = 64 (replicated, broadcast LDS)
            const int t  = d - 64;
            const int rb = ringslot(clampt(t - 1));
            const int re = ringslot(clampt(t));
            const float up = a2 + s_lp[rb * RW + 64];
            const float lf = p2 + s_lp[re * RW + 66 + 63];
            a2 = laexp2(up, lf);
        }
    }

    // extraction: alpha[t_last][u_last] was produced on diagonal d_star
    float v; int owner;
    if (u_last == 64)      { v = a2; owner = 0; }
    else if (u_last >= 32) { v = a1; owner = u_last - 32; }
    else                   { v = a0; owner = u_last; }
    if (lane == owner) {
        const float lpb2 = s_lp[ringslot(t_last) * RW + u_last];
        out[b] = -(v + lpb2) * LN2F;
    }
}

// ---------------------------------------------------------------------------
// Launch: single fused kernel. 8 DP blocks + 8320 A blocks (8 rows each).
// ---------------------------------------------------------------------------
extern "C" void kernel_launch(void* const* d_in, const int* in_sizes, int n_in,
                              void* d_out, int out_size)
{
    const float* logits         = (const float*)d_in[0];
    const int*   targets        = (const int*)d_in[1];
    const int*   logit_lengths  = (const int*)d_in[2];
    const int*   target_lengths = (const int*)d_in[3];
    float*       out            = (float*)d_out;

    const int a_blocks = (Bn * Tn * U1) / 8;   // 8320, one warp per row
    fused_kernel<<<Bn + a_blocks, 256>>>(logits, targets, logit_lengths,
                                         target_lengths, out);
}

// round 11
// speedup vs baseline: 1.3482x; 1.3482x over previous
#include <cuda_runtime.h>
#include <math.h>

// Problem constants (fixed by the reference)
#define Bn    8
#define Tn    128
#define Un    64
#define U1    65
#define Vn    1024
#define BLANKC 1023
#define NEGF  (-1e30f)
#define LOG2E 1.44269504088896340736f
#define LN2F  0.69314718055994530942f
#define SPAD  66        // padded shared row stride (conflict-free diagonals)

// Scratch (BSS zero-init; dead rows stay 0 forever -> deterministic).
__device__ float g_lpb[Bn * Tn * U1];   // log2-domain blank log-probs
__device__ float g_lpe[Bn * Tn * Un];   // log2-domain emit  log-probs

// ---------------------------------------------------------------------------
// Kernel A: one warp per LIVE (b,t,u) row of V=1024 logits.
// Dead rows (t >= logit_len or u > target_len) are skipped entirely — the DP
// never consumes them. No smem -> full occupancy -> HBM roofline.
// ---------------------------------------------------------------------------
__global__ void __launch_bounds__(256)
lse_gather_kernel(const float* __restrict__ logits,
                  const int* __restrict__ targets,
                  const int* __restrict__ logit_lengths,
                  const int* __restrict__ target_lengths)
{
    const int w    = (blockIdx.x * blockDim.x + threadIdx.x) >> 5;
    const int lane = threadIdx.x & 31;
    if (w >= Bn * Tn * U1) return;

    const int b   = w / (Tn * U1);
    const int rem = w - b * (Tn * U1);
    const int t   = rem / U1;
    const int u   = rem - t * U1;

    // Warp-uniform skip of rows the DP never reads.
    if (t >= logit_lengths[b] || u > target_lengths[b]) return;

    const float4* row4 = reinterpret_cast<const float4*>(
        logits + (size_t)w * Vn);

    float4 v[8];
#pragma unroll
    for (int i = 0; i < 8; i++) v[i] = row4[lane + 32 * i];

    float m = -INFINITY;
#pragma unroll
    for (int i = 0; i < 8; i++)
        m = fmaxf(m, fmaxf(fmaxf(v[i].x, v[i].y), fmaxf(v[i].z, v[i].w)));
#pragma unroll
    for (int o = 16; o > 0; o >>= 1)
        m = fmaxf(m, __shfl_xor_sync(0xffffffffu, m, o));

    float s = 0.f;
#pragma unroll
    for (int i = 0; i < 8; i++)
        s += __expf(v[i].x - m) + __expf(v[i].y - m)
           + __expf(v[i].z - m) + __expf(v[i].w - m);
#pragma unroll
    for (int o = 16; o > 0; o >>= 1)
        s += __shfl_xor_sync(0xffffffffu, s, o);

    if (lane == 0) {
        const float lse  = m + logf(s);
        const float* rowf = logits + (size_t)w * Vn;
        g_lpb[w] = (rowf[BLANKC] - lse) * LOG2E;   // log2 domain
        if (u < Un) {
            const int tgt = targets[b * Un + u];
            g_lpe[(b * Tn + t) * Un + u] = (rowf[tgt] - lse) * LOG2E;
        }
    }
}

// ---------------------------------------------------------------------------
// log2-domain logaddexp. Args finite (NEGF sentinel), mn-mx <= 0.
// ---------------------------------------------------------------------------
__device__ __forceinline__ float laexp2(float x, float y)
{
    const float mx = fmaxf(x, y);
    const float mn = fminf(x, y);
    return mx + __log2f(1.0f + exp2f(mn - mx));
}
__device__ __forceinline__ int clampt(int t) { return min(max(t, 0), Tn - 1); }

// ---------------------------------------------------------------------------
// Kernel B: branchless single-warp wavefront, log2 domain.
// u=0 column is blank-only => pure running sum (no logaddexp).
// Lane l owns u = l+1 (a0) and u = l+33 (a1): exactly u = 1..64.
// All updates unconditional; out-of-range cells compute garbage that is
// never consumed by valid cells (consumer at diag d+1 sits at the same t).
// ---------------------------------------------------------------------------
__global__ void __launch_bounds__(128)
rnnt_dp_kernel(const int* __restrict__ logit_lengths,
               const int* __restrict__ target_lengths,
               float* __restrict__ out)
{
    const int b   = blockIdx.x;
    const int tid = threadIdx.x;

    __shared__ float s_lpb[Tn * SPAD];
    __shared__ float s_lpe[Tn * SPAD];

    // ---- preload (coalesced, L2-resident from kernel A; dead entries 0) ----
    {
        const float* lpb_g = g_lpb + b * Tn * U1;
        const float* lpe_g = g_lpe + b * Tn * Un;
        for (int i = tid; i < Tn * U1; i += 128) {
            const int t = i / U1, c = i - t * U1;
            s_lpb[t * SPAD + c] = lpb_g[i];
        }
        for (int i = tid; i < Tn * Un; i += 128) {
            const int t = i / Un, c = i - t * Un;
            s_lpe[t * SPAD + c] = lpe_g[i];
        }
    }
    __syncthreads();
    if (tid >= 32) return;

    const int lane   = tid;
    const int t_last = logit_lengths[b] - 1;
    const int u_last = target_lengths[b];
    const int d_star = t_last + u_last;            // in [95, 191]
    const unsigned FULL = 0xffffffffu;

    float a_u0 = 0.f;                              // u = 0   (alpha[0][0]=0)
    float a0   = NEGF;                             // u = lane + 1
    float a1   = NEGF;                             // u = lane + 33

    for (int d = 1; d <= d_star; d++) {
        // previous-diagonal neighbors
        float p0        = __shfl_up_sync(FULL, a0, 1);    // u-1 for a0
        const float b31 = __shfl_sync(FULL, a0, 31);      // u = 32
        float p1        = __shfl_up_sync(FULL, a1, 1);    // u-1 for a1
        if (lane == 0) { p0 = a_u0; p1 = b31; }           // 2 SELs

        // u = 0: blank-only running sum (cell (t=d, 0))
        a_u0 += s_lpb[clampt(d - 1) * SPAD];

        {   // segment 0: u = lane+1, t = d - u
            const int t  = d - lane - 1;
            const int rb = clampt(t - 1);
            const int re = clampt(t);
            const float up = a0 + s_lpb[rb * SPAD + lane + 1];
            const float lf = p0 + s_lpe[re * SPAD + lane];
            a0 = laexp2(up, lf);
        }
        {   // segment 1: u = lane+33, t = d - u
            const int t  = d - lane - 33;
            const int rb = clampt(t - 1);
            const int re = clampt(t);
            const float up = a1 + s_lpb[rb * SPAD + lane + 33];
            const float lf = p1 + s_lpe[re * SPAD + lane + 32];
            a1 = laexp2(up, lf);
        }
    }

    // ---- extraction: alpha[t_last][u_last] was produced on diagonal d_star
    float v; int owner;
    if (u_last == 0)       { v = a_u0; owner = 0; }
    else if (u_last <= 32) { v = a0; owner = u_last - 1; }
    else                   { v = a1; owner = u_last - 33; }
    if (lane == owner) {
        const float lpb2 = s_lpb[t_last * SPAD + u_last];
        out[b] = -(v + lpb2) * LN2F;
    }
}

// ---------------------------------------------------------------------------
// Launch
// ---------------------------------------------------------------------------
extern "C" void kernel_launch(void* const* d_in, const int* in_sizes, int n_in,
                              void* d_out, int out_size)
{
    const float* logits         = (const float*)d_in[0];
    const int*   targets        = (const int*)d_in[1];
    const int*   logit_lengths  = (const int*)d_in[2];
    const int*   target_lengths = (const int*)d_in[3];
    float*       out            = (float*)d_out;

    const int nrows   = Bn * Tn * U1;          // 66560 rows, one warp each
    const int threads = 256;
    const int blocks  = (nrows * 32 + threads - 1) / threads;

    lse_gather_kernel<<<blocks, threads>>>(logits, targets,
                                           logit_lengths, target_lengths);
    rnnt_dp_kernel<<<Bn, 128>>>(logit_lengths, target_lengths, out);
}

// round 12
// speedup vs baseline: 1.4139x; 1.0487x over previous
#include <cuda_runtime.h>
#include <math.h>

// Problem constants (fixed by the reference)
#define Bn    8
#define Tn    128
#define Un    64
#define U1    65
#define Vn    1024
#define BLANKC 1023
#define NEGF  (-1e30f)
#define LOG2E 1.44269504088896340736f
#define LN2F  0.69314718055994530942f
#define SPAD  66        // padded shared row stride (conflict-free diagonals)

// Scratch (BSS zero-init; dead rows stay 0 forever -> deterministic).
__device__ float g_lpb[Bn * Tn * U1];   // log2-domain blank log-probs
__device__ float g_lpe[Bn * Tn * Un];   // log2-domain emit  log-probs

// ---------------------------------------------------------------------------
// Kernel A: one warp per LIVE (b,t,u) row of V=1024 logits.  (HBM roofline)
// ---------------------------------------------------------------------------
__global__ void __launch_bounds__(256)
lse_gather_kernel(const float* __restrict__ logits,
                  const int* __restrict__ targets,
                  const int* __restrict__ logit_lengths,
                  const int* __restrict__ target_lengths)
{
    const int w    = (blockIdx.x * blockDim.x + threadIdx.x) >> 5;
    const int lane = threadIdx.x & 31;
    if (w >= Bn * Tn * U1) return;

    const int b   = w / (Tn * U1);
    const int rem = w - b * (Tn * U1);
    const int t   = rem / U1;
    const int u   = rem - t * U1;

    // Warp-uniform skip of rows the DP never reads.
    if (t >= logit_lengths[b] || u > target_lengths[b]) return;

    const float4* row4 = reinterpret_cast<const float4*>(
        logits + (size_t)w * Vn);

    float4 v[8];
#pragma unroll
    for (int i = 0; i < 8; i++) v[i] = row4[lane + 32 * i];

    float m = -INFINITY;
#pragma unroll
    for (int i = 0; i < 8; i++)
        m = fmaxf(m, fmaxf(fmaxf(v[i].x, v[i].y), fmaxf(v[i].z, v[i].w)));
#pragma unroll
    for (int o = 16; o > 0; o >>= 1)
        m = fmaxf(m, __shfl_xor_sync(0xffffffffu, m, o));

    float s = 0.f;
#pragma unroll
    for (int i = 0; i < 8; i++)
        s += __expf(v[i].x - m) + __expf(v[i].y - m)
           + __expf(v[i].z - m) + __expf(v[i].w - m);
#pragma unroll
    for (int o = 16; o > 0; o >>= 1)
        s += __shfl_xor_sync(0xffffffffu, s, o);

    if (lane == 0) {
        const float lse  = m + logf(s);
        const float* rowf = logits + (size_t)w * Vn;
        g_lpb[w] = (rowf[BLANKC] - lse) * LOG2E;   // log2 domain
        if (u < Un) {
            const int tgt = targets[b * Un + u];
            g_lpe[(b * Tn + t) * Un + u] = (rowf[tgt] - lse) * LOG2E;
        }
    }
}

// ---------------------------------------------------------------------------
// MUFU-only log2-domain logaddexp.
//   ex2.approx / lg2.approx  ->  MUFU.EX2 / MUFU.LG2  (16 cyc each, HW)
// Args finite (NEGF sentinel), mn-mx <= 0 so ex2 in [0,1], lg2 arg in [1,2].
// ---------------------------------------------------------------------------
__device__ __forceinline__ float ex2_fast(float x) {
    float r; asm("ex2.approx.ftz.f32 %0, %1;" : "=f"(r) : "f"(x)); return r;
}
__device__ __forceinline__ float lg2_fast(float x) {
    float r; asm("lg2.approx.ftz.f32 %0, %1;" : "=f"(r) : "f"(x)); return r;
}
__device__ __forceinline__ float laexp2(float x, float y)
{
    const float mx = fmaxf(x, y);
    const float mn = fminf(x, y);
    return mx + lg2_fast(1.0f + ex2_fast(mn - mx));
}
__device__ __forceinline__ int clampt(int t) { return min(max(t, 0), Tn - 1); }

// ---------------------------------------------------------------------------
// Kernel B: branchless single-warp wavefront, log2 domain, pure-MUFU laexp.
// u=0 column is blank-only => running sum. Lane l owns u=l+1 and u=l+33.
// All updates unconditional; out-of-range cells compute harmless garbage
// never consumed by valid cells.
// ---------------------------------------------------------------------------
__global__ void __launch_bounds__(128)
rnnt_dp_kernel(const int* __restrict__ logit_lengths,
               const int* __restrict__ target_lengths,
               float* __restrict__ out)
{
    const int b   = blockIdx.x;
    const int tid = threadIdx.x;

    __shared__ float s_lpb[Tn * SPAD];
    __shared__ float s_lpe[Tn * SPAD];

    // ---- preload (coalesced, L2-resident from kernel A; dead entries 0) ----
    {
        const float* lpb_g = g_lpb + b * Tn * U1;
        const float* lpe_g = g_lpe + b * Tn * Un;
        for (int i = tid; i < Tn * U1; i += 128) {
            const int t = i / U1, c = i - t * U1;
            s_lpb[t * SPAD + c] = lpb_g[i];
        }
        for (int i = tid; i < Tn * Un; i += 128) {
            const int t = i / Un, c = i - t * Un;
            s_lpe[t * SPAD + c] = lpe_g[i];
        }
    }
    __syncthreads();
    if (tid >= 32) return;

    const int lane   = tid;
    const int t_last = logit_lengths[b] - 1;
    const int u_last = target_lengths[b];
    const int d_star = t_last + u_last;            // in [95, 191]
    const unsigned FULL = 0xffffffffu;

    float a_u0 = 0.f;                              // u = 0   (alpha[0][0]=0)
    float a0   = NEGF;                             // u = lane + 1
    float a1   = NEGF;                             // u = lane + 33

    for (int d = 1; d <= d_star; d++) {
        // previous-diagonal neighbors
        float p0        = __shfl_up_sync(FULL, a0, 1);    // u-1 for a0
        const float b31 = __shfl_sync(FULL, a0, 31);      // u = 32
        float p1        = __shfl_up_sync(FULL, a1, 1);    // u-1 for a1
        if (lane == 0) { p0 = a_u0; p1 = b31; }           // 2 SELs

        // u = 0: blank-only running sum (cell (t=d, 0))
        a_u0 += s_lpb[clampt(d - 1) * SPAD];

        {   // segment 0: u = lane+1, t = d - u
            const int t  = d - lane - 1;
            const int rb = clampt(t - 1);
            const int re = clampt(t);
            const float up = a0 + s_lpb[rb * SPAD + lane + 1];
            const float lf = p0 + s_lpe[re * SPAD + lane];
            a0 = laexp2(up, lf);
        }
        {   // segment 1: u = lane+33, t = d - u
            const int t  = d - lane - 33;
            const int rb = clampt(t - 1);
            const int re = clampt(t);
            const float up = a1 + s_lpb[rb * SPAD + lane + 33];
            const float lf = p1 + s_lpe[re * SPAD + lane + 32];
            a1 = laexp2(up, lf);
        }
    }

    // ---- extraction: alpha[t_last][u_last] was produced on diagonal d_star
    float v; int owner;
    if (u_last == 0)       { v = a_u0; owner = 0; }
    else if (u_last <= 32) { v = a0; owner = u_last - 1; }
    else                   { v = a1; owner = u_last - 33; }
    if (lane == owner) {
        const float lpb2 = s_lpb[t_last * SPAD + u_last];
        out[b] = -(v + lpb2) * LN2F;
    }
}

// ---------------------------------------------------------------------------
// Launch
// ---------------------------------------------------------------------------
extern "C" void kernel_launch(void* const* d_in, const int* in_sizes, int n_in,
                              void* d_out, int out_size)
{
    const float* logits         = (const float*)d_in[0];
    const int*   targets        = (const int*)d_in[1];
    const int*   logit_lengths  = (const int*)d_in[2];
    const int*   target_lengths = (const int*)d_in[3];
    float*       out            = (float*)d_out;

    const int nrows   = Bn * Tn * U1;          // 66560 rows, one warp each
    const int threads = 256;
    const int blocks  = (nrows * 32 + threads - 1) / threads;

    lse_gather_kernel<<<blocks, threads>>>(logits, targets,
                                           logit_lengths, target_lengths);
    rnnt_dp_kernel<<<Bn, 128>>>(logit_lengths, target_lengths, out);
}